// round 3
// baseline (speedup 1.0000x reference)
#include <cuda_runtime.h>

#define NH 8
#define DD 1024
#define MM 2048
#define PIX 49152        // 128*128*3
#define PIX4 12288
#define MS 8             // m-splits for the V pass

__device__ float g_q[NH*DD];
__device__ float g_t[NH*DD];
__device__ float g_c[NH];
__device__ float g_logits[NH*MM];
__device__ float g_wt[MM*NH];              // softmax weights, transposed [m][h]
__device__ float4 g_outp[MS*NH*PIX4];      // 12.6 MB partials

__device__ __forceinline__ unsigned long long pk2(float a, float b){
    unsigned long long r;
    asm("mov.b64 %0, {%1, %2};" : "=l"(r) : "f"(a), "f"(b));
    return r;
}
__device__ __forceinline__ void fma2(unsigned long long &acc, unsigned long long v, unsigned long long w){
    asm("fma.rn.f32x2 %0, %1, %2, %0;" : "+l"(acc) : "l"(v), "l"(w));
}
__device__ __forceinline__ void upk2(unsigned long long p, float &a, float &b){
    asm("mov.b64 {%0, %1}, %2;" : "=f"(a), "=f"(b) : "l"(p));
}

// ---------------------------------------------------------------------------
// Kernel A: q[h,e] = Q . WQ[h,e,:] + bQ[h,e]   (warp per (h,e))
//           also zeroes g_t / g_c for this graph replay
// ---------------------------------------------------------------------------
__global__ void proj_q_kernel(const float* __restrict__ Q,
                              const float* __restrict__ WQ,
                              const float* __restrict__ bQ) {
    int tid = threadIdx.x;
    int gid = (blockIdx.y * gridDim.x + blockIdx.x) * blockDim.x + tid;
    if (gid < NH*DD) g_t[gid] = 0.f;
    if (gid < NH)    g_c[gid] = 0.f;

    int h = blockIdx.y;
    int e = blockIdx.x * 8 + (tid >> 5);
    int lane = tid & 31;
    const float4* W4 = (const float4*)WQ + (size_t)h*(DD*DD/4) + (size_t)e*(DD/4);
    const float4* Q4 = (const float4*)Q;
    float acc = 0.f;
    #pragma unroll
    for (int i = 0; i < 8; i++) {
        float4 w = W4[lane + i*32];
        float4 q = Q4[lane + i*32];
        acc += w.x*q.x + w.y*q.y + w.z*q.z + w.w*q.w;
    }
    #pragma unroll
    for (int o = 16; o; o >>= 1) acc += __shfl_xor_sync(0xffffffffu, acc, o);
    if (lane == 0) g_q[h*DD + e] = acc + bQ[h*DD + e];
}

// ---------------------------------------------------------------------------
// Kernel B: t[h,d] = sum_e q[h,e] * WK[h,e,d]   (thread per d, e-split + atomic)
//           c[h]   = sum_e q[h,e] * bK[h,e]
// ---------------------------------------------------------------------------
__global__ void proj_t_kernel(const float* __restrict__ WK,
                              const float* __restrict__ bK) {
    int tid = threadIdx.x;
    int d  = blockIdx.x * 256 + tid;
    int h  = blockIdx.y;
    int e0 = blockIdx.z * 128;
    const float* Wp = WK + (size_t)h*DD*DD + (size_t)e0*DD + d;
    const float* qp = g_q + h*DD + e0;
    float acc = 0.f;
    #pragma unroll 8
    for (int e = 0; e < 128; e++)
        acc = fmaf(qp[e], Wp[(size_t)e*DD], acc);
    atomicAdd(&g_t[h*DD + d], acc);

    if (blockIdx.x == 0) {
        __shared__ float red[256];
        float v = (tid < 128) ? qp[tid] * bK[h*DD + e0 + tid] : 0.f;
        red[tid] = v;
        __syncthreads();
        for (int s = 128; s; s >>= 1) {
            if (tid < s) red[tid] += red[tid + s];
            __syncthreads();
        }
        if (tid == 0) atomicAdd(&g_c[h], red[0]);
    }
}

// ---------------------------------------------------------------------------
// Kernel C: logits[h,m] = (K[m,:] . t[h,:] + c[h]) / 1024   (warp per m)
// ---------------------------------------------------------------------------
__global__ void logits_kernel(const float* __restrict__ K) {
    __shared__ float4 ts4[NH*DD/4];   // 32 KB
    int tid = threadIdx.x;
    for (int i = tid; i < NH*DD/4; i += 256) ts4[i] = ((const float4*)g_t)[i];
    __syncthreads();

    int m = blockIdx.x * 8 + (tid >> 5);
    int lane = tid & 31;
    const float4* K4 = (const float4*)K + (size_t)m*(DD/4);
    float acc[NH];
    #pragma unroll
    for (int h = 0; h < NH; h++) acc[h] = 0.f;
    #pragma unroll
    for (int i = 0; i < 8; i++) {
        float4 k4 = K4[lane + i*32];
        #pragma unroll
        for (int h = 0; h < NH; h++) {
            float4 t4 = ts4[h*256 + lane + i*32];
            acc[h] += k4.x*t4.x + k4.y*t4.y + k4.z*t4.z + k4.w*t4.w;
        }
    }
    #pragma unroll
    for (int h = 0; h < NH; h++) {
        #pragma unroll
        for (int o = 16; o; o >>= 1) acc[h] += __shfl_xor_sync(0xffffffffu, acc[h], o);
    }
    if (lane == 0) {
        #pragma unroll
        for (int h = 0; h < NH; h++)
            g_logits[h*MM + m] = (acc[h] + g_c[h]) * (1.0f/1024.0f);
    }
}

// ---------------------------------------------------------------------------
// Kernel D: softmax over m per head; writes transposed weights g_wt[m][h]
// ---------------------------------------------------------------------------
__global__ void softmax_kernel() {
    int h = blockIdx.x, tid = threadIdx.x;
    __shared__ float red[256];
    float l[8];
    float mx = -1e30f;
    #pragma unroll
    for (int i = 0; i < 8; i++) {
        l[i] = g_logits[h*MM + tid + i*256];
        mx = fmaxf(mx, l[i]);
    }
    red[tid] = mx; __syncthreads();
    for (int s = 128; s; s >>= 1) {
        if (tid < s) red[tid] = fmaxf(red[tid], red[tid + s]);
        __syncthreads();
    }
    mx = red[0]; __syncthreads();
    float sum = 0.f;
    #pragma unroll
    for (int i = 0; i < 8; i++) { l[i] = expf(l[i] - mx); sum += l[i]; }
    red[tid] = sum; __syncthreads();
    for (int s = 128; s; s >>= 1) {
        if (tid < s) red[tid] += red[tid + s];
        __syncthreads();
    }
    float inv = 1.0f / red[0];
    #pragma unroll
    for (int i = 0; i < 8; i++)
        g_wt[(tid + i*256)*NH + h] = l[i] * inv;
}

// ---------------------------------------------------------------------------
// Kernel E: partial[s][h][:] = sum_{m in slice s} w[h,m] * V[m,:]
//   DRAM-bound V stream (402 MB). float4 loads, 8 heads x f32x2 packed FMAs.
// ---------------------------------------------------------------------------
__global__ void __launch_bounds__(256) wsum_kernel(const float* __restrict__ V) {
    __shared__ unsigned long long w2s[256*NH];   // 16 KB, weights pre-packed (w,w)
    int tid = threadIdx.x;
    int m0 = blockIdx.y * 256;
    for (int i = tid; i < 256*NH; i += 256) {
        float w = g_wt[m0*NH + i];
        w2s[i] = pk2(w, w);
    }
    __syncthreads();

    int jj = blockIdx.x * 256 + tid;            // float4 index within PIX4
    const float4* V4 = (const float4*)V + jj;
    unsigned long long a0[NH], a1[NH];
    #pragma unroll
    for (int h = 0; h < NH; h++) { a0[h] = 0ull; a1[h] = 0ull; }

    #pragma unroll 1
    for (int lm = 0; lm < 256; lm += 4) {
        float4 v[4];
        #pragma unroll
        for (int u = 0; u < 4; u++)
            v[u] = V4[(m0 + lm + u) * PIX4];
        #pragma unroll
        for (int u = 0; u < 4; u++) {
            unsigned long long v01 = pk2(v[u].x, v[u].y);
            unsigned long long v23 = pk2(v[u].z, v[u].w);
            const ulonglong2* wr = (const ulonglong2*)&w2s[(lm + u)*NH];
            #pragma unroll
            for (int h2 = 0; h2 < 4; h2++) {
                ulonglong2 wp = wr[h2];
                fma2(a0[2*h2],   v01, wp.x);
                fma2(a1[2*h2],   v23, wp.x);
                fma2(a0[2*h2+1], v01, wp.y);
                fma2(a1[2*h2+1], v23, wp.y);
            }
        }
    }

    int s = blockIdx.y;
    #pragma unroll
    for (int h = 0; h < NH; h++) {
        float x, y, z, w;
        upk2(a0[h], x, y);
        upk2(a1[h], z, w);
        g_outp[(s*NH + h)*PIX4 + jj] = make_float4(x, y, z, w);
    }
}

// ---------------------------------------------------------------------------
// Kernel F: out[h][:] = sum_s partial[s][h][:]
// ---------------------------------------------------------------------------
__global__ void reduce_kernel(float4* __restrict__ out4) {
    int idx = blockIdx.x * 256 + threadIdx.x;   // over NH*PIX4 = 98304
    int h  = idx / PIX4;
    int jj = idx % PIX4;
    float4 s = make_float4(0.f, 0.f, 0.f, 0.f);
    #pragma unroll
    for (int sp = 0; sp < MS; sp++) {
        float4 p = g_outp[(sp*NH + h)*PIX4 + jj];
        s.x += p.x; s.y += p.y; s.z += p.z; s.w += p.w;
    }
    out4[idx] = s;
}

extern "C" void kernel_launch(void* const* d_in, const int* in_sizes, int n_in,
                              void* d_out, int out_size) {
    const float* Q  = (const float*)d_in[0];
    const float* K  = (const float*)d_in[1];
    const float* V  = (const float*)d_in[2];
    const float* WQ = (const float*)d_in[3];
    const float* bQ = (const float*)d_in[4];
    const float* WK = (const float*)d_in[5];
    const float* bK = (const float*)d_in[6];

    proj_q_kernel<<<dim3(128, 8), 256>>>(Q, WQ, bQ);
    proj_t_kernel<<<dim3(4, 8, 8), 256>>>(WK, bK);
    logits_kernel<<<256, 256>>>(K);
    softmax_kernel<<<8, 256>>>();
    wsum_kernel<<<dim3(48, MS), 256>>>(V);
    reduce_kernel<<<384, 256>>>((float4*)d_out);
}

// round 4
// speedup vs baseline: 1.0976x; 1.0976x over previous
#include <cuda_runtime.h>

#define NH 8
#define DD 1024
#define MM 2048
#define PIX4 12288      // 128*128*3 / 4
#define MS 32           // m-splits for the V pass
#define MSLICE 64       // m per wsum block (MM/MS)

__device__ float g_q[NH*DD];
__device__ float g_t[NH*DD];
__device__ float g_c[NH];
__device__ float g_sums[NH];
__device__ float g_wt[MM*NH];   // unnormalized exp weights, transposed [m][h]

__device__ __forceinline__ unsigned long long pk2(float a, float b){
    unsigned long long r;
    asm("mov.b64 %0, {%1, %2};" : "=l"(r) : "f"(a), "f"(b));
    return r;
}
__device__ __forceinline__ void fma2(unsigned long long &acc, unsigned long long v, unsigned long long w){
    asm("fma.rn.f32x2 %0, %1, %2, %0;" : "+l"(acc) : "l"(v), "l"(w));
}
__device__ __forceinline__ void upk2(unsigned long long p, float &a, float &b){
    asm("mov.b64 {%0, %1}, %2;" : "=f"(a), "=f"(b) : "l"(p));
}

// ---------------------------------------------------------------------------
// Kernel A: q[h,e] = Q . WQ[h,e,:] + bQ[h,e]   (warp per (h,e))
//           also zeroes g_t / g_c / g_sums for this graph replay
// ---------------------------------------------------------------------------
__global__ void proj_q_kernel(const float* __restrict__ Q,
                              const float* __restrict__ WQ,
                              const float* __restrict__ bQ) {
    int tid = threadIdx.x;
    int gid = (blockIdx.y * gridDim.x + blockIdx.x) * blockDim.x + tid;
    if (gid < NH*DD) g_t[gid] = 0.f;
    if (gid < NH) { g_c[gid] = 0.f; g_sums[gid] = 0.f; }

    int h = blockIdx.y;
    int e = blockIdx.x * 8 + (tid >> 5);
    int lane = tid & 31;
    const float4* W4 = (const float4*)WQ + (size_t)h*(DD*DD/4) + (size_t)e*(DD/4);
    const float4* Q4 = (const float4*)Q;
    float acc = 0.f;
    #pragma unroll
    for (int i = 0; i < 8; i++) {
        float4 w = W4[lane + i*32];
        float4 q = Q4[lane + i*32];
        acc += w.x*q.x + w.y*q.y + w.z*q.z + w.w*q.w;
    }
    #pragma unroll
    for (int o = 16; o; o >>= 1) acc += __shfl_xor_sync(0xffffffffu, acc, o);
    if (lane == 0) g_q[h*DD + e] = acc + bQ[h*DD + e];
}

// ---------------------------------------------------------------------------
// Kernel B: t[h,d] = sum_e q[h,e] * WK[h,e,d]   (thread per d, e-split + atomic)
//           c[h]   = sum_e q[h,e] * bK[h,e]
// ---------------------------------------------------------------------------
__global__ void proj_t_kernel(const float* __restrict__ WK,
                              const float* __restrict__ bK) {
    int tid = threadIdx.x;
    int d  = blockIdx.x * 256 + tid;
    int h  = blockIdx.y;
    int e0 = blockIdx.z * 128;
    const float* Wp = WK + (size_t)h*DD*DD + (size_t)e0*DD + d;
    const float* qp = g_q + h*DD + e0;
    float acc = 0.f;
    #pragma unroll 8
    for (int e = 0; e < 128; e++)
        acc = fmaf(qp[e], Wp[(size_t)e*DD], acc);
    atomicAdd(&g_t[h*DD + d], acc);

    if (blockIdx.x == 0) {
        __shared__ float red[256];
        float v = (tid < 128) ? qp[tid] * bK[h*DD + e0 + tid] : 0.f;
        red[tid] = v;
        __syncthreads();
        for (int s = 128; s; s >>= 1) {
            if (tid < s) red[tid] += red[tid + s];
            __syncthreads();
        }
        if (tid == 0) atomicAdd(&g_c[h], red[0]);
    }
}

// ---------------------------------------------------------------------------
// Kernel C: fused logits + exp (unnormalized softmax) + per-head sum
//   g_wt[m][h] = exp((K[m,:].t[h,:] + c[h]) / 1024)   (no max-sub: |l| < 0.1)
//   g_sums[h] += sum_m g_wt[m][h]
//   Also zero-inits d_out (REDG target for wsum).
// ---------------------------------------------------------------------------
__global__ void logits_kernel(const float* __restrict__ K,
                              float4* __restrict__ out4) {
    __shared__ float4 ts4[NH*DD/4];   // 32 KB
    __shared__ float ws[8][NH];
    int tid = threadIdx.x;
    for (int i = tid; i < NH*DD/4; i += 256) ts4[i] = ((const float4*)g_t)[i];

    // zero d_out (256 blocks x 256 threads cover 98304 float4 in <=2 steps)
    for (int idx = blockIdx.x * 256 + tid; idx < NH*PIX4; idx += 256*256)
        out4[idx] = make_float4(0.f, 0.f, 0.f, 0.f);
    __syncthreads();

    int wid = tid >> 5;
    int m = blockIdx.x * 8 + wid;
    int lane = tid & 31;
    const float4* K4 = (const float4*)K + (size_t)m*(DD/4);
    float acc[NH];
    #pragma unroll
    for (int h = 0; h < NH; h++) acc[h] = 0.f;
    #pragma unroll
    for (int i = 0; i < 8; i++) {
        float4 k4 = K4[lane + i*32];
        #pragma unroll
        for (int h = 0; h < NH; h++) {
            float4 t4 = ts4[h*256 + lane + i*32];
            acc[h] += k4.x*t4.x + k4.y*t4.y + k4.z*t4.z + k4.w*t4.w;
        }
    }
    #pragma unroll
    for (int h = 0; h < NH; h++) {
        #pragma unroll
        for (int o = 16; o; o >>= 1) acc[h] += __shfl_xor_sync(0xffffffffu, acc[h], o);
    }
    if (lane == 0) {
        #pragma unroll
        for (int h = 0; h < NH; h++) {
            float w = expf((acc[h] + g_c[h]) * (1.0f/1024.0f));
            g_wt[m*NH + h] = w;
            ws[wid][h] = w;
        }
    }
    __syncthreads();
    if (tid < NH) {
        float s = 0.f;
        #pragma unroll
        for (int w8 = 0; w8 < 8; w8++) s += ws[w8][tid];
        atomicAdd(&g_sums[tid], s);
    }
}

// ---------------------------------------------------------------------------
// Kernel D: out[h][:] += sum_{m in slice} (w[h,m]/sum[h]) * V[m,:]
//   DRAM-bound V stream (402 MB). float4 ldcs loads, MLP=8,
//   8 heads x f32x2 packed FMAs, REDG v4 straight into d_out (L2-resident).
// ---------------------------------------------------------------------------
__global__ void __launch_bounds__(256) wsum_kernel(const float* __restrict__ V,
                                                   float4* __restrict__ out4) {
    __shared__ unsigned long long w2s[MSLICE*NH];   // 4 KB, normalized (w,w)
    int tid = threadIdx.x;
    int m0 = blockIdx.y * MSLICE;

    float inv[NH];
    #pragma unroll
    for (int h = 0; h < NH; h++) inv[h] = __fdividef(1.0f, g_sums[h]);
    for (int i = tid; i < MSLICE*NH; i += 256) {
        float w = g_wt[m0*NH + i] * inv[i & 7];
        w2s[i] = pk2(w, w);
    }
    __syncthreads();

    int jj = blockIdx.x * 256 + tid;            // float4 index within PIX4
    const float4* V4 = (const float4*)V + jj;
    unsigned long long a0[NH], a1[NH];
    #pragma unroll
    for (int h = 0; h < NH; h++) { a0[h] = 0ull; a1[h] = 0ull; }

    #pragma unroll 1
    for (int lm = 0; lm < MSLICE; lm += 8) {
        float4 v[8];
        #pragma unroll
        for (int u = 0; u < 8; u++)
            v[u] = __ldcs(&V4[(size_t)(m0 + lm + u) * PIX4]);
        #pragma unroll
        for (int u = 0; u < 8; u++) {
            unsigned long long v01 = pk2(v[u].x, v[u].y);
            unsigned long long v23 = pk2(v[u].z, v[u].w);
            const ulonglong2* wr = (const ulonglong2*)&w2s[(lm + u)*NH];
            #pragma unroll
            for (int h2 = 0; h2 < 4; h2++) {
                ulonglong2 wp = wr[h2];
                fma2(a0[2*h2],   v01, wp.x);
                fma2(a1[2*h2],   v23, wp.x);
                fma2(a0[2*h2+1], v01, wp.y);
                fma2(a1[2*h2+1], v23, wp.y);
            }
        }
    }

    #pragma unroll
    for (int h = 0; h < NH; h++) {
        float x, y, z, w;
        upk2(a0[h], x, y);
        upk2(a1[h], z, w);
        float* p = (float*)&out4[h*PIX4 + jj];
        asm volatile("red.global.add.v4.f32 [%0], {%1, %2, %3, %4};"
                     :: "l"(p), "f"(x), "f"(y), "f"(z), "f"(w) : "memory");
    }
}

extern "C" void kernel_launch(void* const* d_in, const int* in_sizes, int n_in,
                              void* d_out, int out_size) {
    const float* Q  = (const float*)d_in[0];
    const float* K  = (const float*)d_in[1];
    const float* V  = (const float*)d_in[2];
    const float* WQ = (const float*)d_in[3];
    const float* bQ = (const float*)d_in[4];
    const float* WK = (const float*)d_in[5];
    const float* bK = (const float*)d_in[6];

    proj_q_kernel<<<dim3(128, 8), 256>>>(Q, WQ, bQ);
    proj_t_kernel<<<dim3(4, 8, 8), 256>>>(WK, bK);
    logits_kernel<<<256, 256>>>(K, (float4*)d_out);
    wsum_kernel<<<dim3(48, MS), 256>>>(V, (float4*)d_out);
}

// round 5
// speedup vs baseline: 1.1754x; 1.0709x over previous
#include <cuda_runtime.h>

#define NH 8
#define DD 1024
#define MM 2048
#define PIX4 12288      // 128*128*3 / 4
#define MSLICE 64       // m per wsum tile
#define XT 48           // x-tiles (PIX4 / 256)
#define NTILES (XT * (MM / MSLICE))   // 48*32 = 1536
#define PGRID 444       // 148 SMs x 3 blocks, persistent

__device__ float g_q[NH*DD];
__device__ float g_t[NH*DD];
__device__ float g_c[NH];
__device__ float g_sums[NH];
__device__ float g_wt[MM*NH];   // unnormalized exp weights, transposed [m][h]
__device__ int   g_ctr;

__device__ __forceinline__ unsigned long long pk2(float a, float b){
    unsigned long long r;
    asm("mov.b64 %0, {%1, %2};" : "=l"(r) : "f"(a), "f"(b));
    return r;
}
__device__ __forceinline__ void fma2(unsigned long long &acc, unsigned long long v, unsigned long long w){
    asm("fma.rn.f32x2 %0, %1, %2, %0;" : "+l"(acc) : "l"(v), "l"(w));
}
__device__ __forceinline__ void upk2(unsigned long long p, float &a, float &b){
    asm("mov.b64 {%0, %1}, %2;" : "=f"(a), "=f"(b) : "l"(p));
}

// ---------------------------------------------------------------------------
// Kernel A: q[h,e] = Q . WQ[h,e,:] + bQ[h,e]   (warp per (h,e))
//           also zeroes g_t / g_c / g_sums for this graph replay
// ---------------------------------------------------------------------------
__global__ void proj_q_kernel(const float* __restrict__ Q,
                              const float* __restrict__ WQ,
                              const float* __restrict__ bQ) {
    int tid = threadIdx.x;
    int gid = (blockIdx.y * gridDim.x + blockIdx.x) * blockDim.x + tid;
    if (gid < NH*DD) g_t[gid] = 0.f;
    if (gid < NH) { g_c[gid] = 0.f; g_sums[gid] = 0.f; }

    int h = blockIdx.y;
    int e = blockIdx.x * 8 + (tid >> 5);
    int lane = tid & 31;
    const float4* W4 = (const float4*)WQ + (size_t)h*(DD*DD/4) + (size_t)e*(DD/4);
    const float4* Q4 = (const float4*)Q;
    float acc = 0.f;
    #pragma unroll
    for (int i = 0; i < 8; i++) {
        float4 w = __ldcs(&W4[lane + i*32]);
        float4 q = Q4[lane + i*32];
        acc += w.x*q.x + w.y*q.y + w.z*q.z + w.w*q.w;
    }
    #pragma unroll
    for (int o = 16; o; o >>= 1) acc += __shfl_xor_sync(0xffffffffu, acc, o);
    if (lane == 0) g_q[h*DD + e] = acc + bQ[h*DD + e];
}

// ---------------------------------------------------------------------------
// Kernel B: t[h,d] += sum_{e in chunk} q[h,e] * WK[h,e,d]
//   float4 along d (thread tid -> d = 4*tid..4*tid+3), e-chunks of 32,
//   red.global.add.v4 into g_t. Bias-dot partial c[h] folded in.
// ---------------------------------------------------------------------------
#define ESL 32
__global__ void proj_t_kernel(const float* __restrict__ WK,
                              const float* __restrict__ bK) {
    int tid = threadIdx.x;
    int h  = blockIdx.y;
    int e0 = blockIdx.x * ESL;
    const float4* Wp = (const float4*)(WK + (size_t)h*DD*DD + (size_t)e0*DD) + tid;
    const float* qp = g_q + h*DD + e0;
    float4 acc = make_float4(0.f, 0.f, 0.f, 0.f);
    #pragma unroll 8
    for (int e = 0; e < ESL; e++) {
        float qe = qp[e];
        float4 w = __ldcs(&Wp[(size_t)e*(DD/4)]);
        acc.x = fmaf(qe, w.x, acc.x);
        acc.y = fmaf(qe, w.y, acc.y);
        acc.z = fmaf(qe, w.z, acc.z);
        acc.w = fmaf(qe, w.w, acc.w);
    }
    float* p = &g_t[h*DD + tid*4];
    asm volatile("red.global.add.v4.f32 [%0], {%1, %2, %3, %4};"
                 :: "l"(p), "f"(acc.x), "f"(acc.y), "f"(acc.z), "f"(acc.w) : "memory");

    if (tid < 32) {
        float v = qp[tid] * bK[h*DD + e0 + tid];
        #pragma unroll
        for (int o = 16; o; o >>= 1) v += __shfl_xor_sync(0xffffffffu, v, o);
        if (tid == 0) atomicAdd(&g_c[h], v);
    }
}

// ---------------------------------------------------------------------------
// Kernel C: fused logits + exp (unnormalized softmax) + per-head sum
//   g_wt[m][h] = exp((K[m,:].t[h,:] + c[h]) / 1024)   (no max-sub: |l| small)
//   Zero-inits d_out and resets the persistent-tile counter.
// ---------------------------------------------------------------------------
__global__ void logits_kernel(const float* __restrict__ K,
                              float4* __restrict__ out4) {
    __shared__ float4 ts4[NH*DD/4];   // 32 KB
    __shared__ float ws[8][NH];
    int tid = threadIdx.x;
    if (blockIdx.x == 0 && tid == 0) g_ctr = 0;
    for (int i = tid; i < NH*DD/4; i += 256) ts4[i] = ((const float4*)g_t)[i];

    for (int idx = blockIdx.x * 256 + tid; idx < NH*PIX4; idx += 256*256)
        out4[idx] = make_float4(0.f, 0.f, 0.f, 0.f);
    __syncthreads();

    int wid = tid >> 5;
    int m = blockIdx.x * 8 + wid;
    int lane = tid & 31;
    const float4* K4 = (const float4*)K + (size_t)m*(DD/4);
    float acc[NH];
    #pragma unroll
    for (int h = 0; h < NH; h++) acc[h] = 0.f;
    #pragma unroll
    for (int i = 0; i < 8; i++) {
        float4 k4 = K4[lane + i*32];
        #pragma unroll
        for (int h = 0; h < NH; h++) {
            float4 t4 = ts4[h*256 + lane + i*32];
            acc[h] += k4.x*t4.x + k4.y*t4.y + k4.z*t4.z + k4.w*t4.w;
        }
    }
    #pragma unroll
    for (int h = 0; h < NH; h++) {
        #pragma unroll
        for (int o = 16; o; o >>= 1) acc[h] += __shfl_xor_sync(0xffffffffu, acc[h], o);
    }
    if (lane == 0) {
        #pragma unroll
        for (int h = 0; h < NH; h++) {
            float w = expf((acc[h] + g_c[h]) * (1.0f/1024.0f));
            g_wt[m*NH + h] = w;
            ws[wid][h] = w;
        }
    }
    __syncthreads();
    if (tid < NH) {
        float s = 0.f;
        #pragma unroll
        for (int w8 = 0; w8 < 8; w8++) s += ws[w8][tid];
        atomicAdd(&g_sums[tid], s);
    }
}

// ---------------------------------------------------------------------------
// Kernel D: persistent ticket-scheduled weighted V sum.
//   out[h][:] += sum_m (w[h,m]/sum[h]) * V[m,:]
//   Double-buffered (4+4) __ldcs float4 loads, f32x2 FMAs, REDG.v4 output.
// ---------------------------------------------------------------------------
__device__ __forceinline__ void accum4(const float4 v[4],
                                       const unsigned long long* __restrict__ w2s,
                                       int lm,
                                       unsigned long long a0[NH],
                                       unsigned long long a1[NH]) {
    #pragma unroll
    for (int u = 0; u < 4; u++) {
        unsigned long long v01 = pk2(v[u].x, v[u].y);
        unsigned long long v23 = pk2(v[u].z, v[u].w);
        const ulonglong2* wr = (const ulonglong2*)&w2s[(lm + u)*NH];
        #pragma unroll
        for (int h2 = 0; h2 < 4; h2++) {
            ulonglong2 wp = wr[h2];
            fma2(a0[2*h2],   v01, wp.x);
            fma2(a1[2*h2],   v23, wp.x);
            fma2(a0[2*h2+1], v01, wp.y);
            fma2(a1[2*h2+1], v23, wp.y);
        }
    }
}

__global__ void __launch_bounds__(256, 3) wsum_kernel(const float* __restrict__ V,
                                                      float4* __restrict__ out4) {
    __shared__ unsigned long long w2s[MSLICE*NH];   // 4 KB, normalized (w,w)
    __shared__ int s_tile;
    int tid = threadIdx.x;

    for (;;) {
        if (tid == 0) s_tile = atomicAdd(&g_ctr, 1);
        __syncthreads();                 // publishes ticket; fences prev w2s reads
        int t = s_tile;
        if (t >= NTILES) break;
        int s  = t / XT;
        int xb = t - s*XT;
        int m0 = s * MSLICE;

        for (int i = tid; i < MSLICE*NH; i += 256) {
            float w = __fdividef(g_wt[m0*NH + i], g_sums[i & 7]);
            w2s[i] = pk2(w, w);
        }
        __syncthreads();

        int jj = xb*256 + tid;
        const float4* V4 = (const float4*)V + (size_t)m0*PIX4 + jj;
        unsigned long long a0[NH], a1[NH];
        #pragma unroll
        for (int h = 0; h < NH; h++) { a0[h] = 0ull; a1[h] = 0ull; }

        float4 va[4], vb[4];
        #pragma unroll
        for (int u = 0; u < 4; u++) va[u] = __ldcs(&V4[(size_t)u * PIX4]);

        #pragma unroll 1
        for (int lm = 0; lm < MSLICE; lm += 8) {
            #pragma unroll
            for (int u = 0; u < 4; u++)
                vb[u] = __ldcs(&V4[(size_t)(lm + 4 + u) * PIX4]);
            accum4(va, w2s, lm, a0, a1);
            if (lm + 8 < MSLICE) {
                #pragma unroll
                for (int u = 0; u < 4; u++)
                    va[u] = __ldcs(&V4[(size_t)(lm + 8 + u) * PIX4]);
            }
            accum4(vb, w2s, lm + 4, a0, a1);
        }

        #pragma unroll
        for (int h = 0; h < NH; h++) {
            float x, y, z, w;
            upk2(a0[h], x, y);
            upk2(a1[h], z, w);
            float* p = (float*)&out4[h*PIX4 + jj];
            asm volatile("red.global.add.v4.f32 [%0], {%1, %2, %3, %4};"
                         :: "l"(p), "f"(x), "f"(y), "f"(z), "f"(w) : "memory");
        }
    }
}

extern "C" void kernel_launch(void* const* d_in, const int* in_sizes, int n_in,
                              void* d_out, int out_size) {
    const float* Q  = (const float*)d_in[0];
    const float* K  = (const float*)d_in[1];
    const float* V  = (const float*)d_in[2];
    const float* WQ = (const float*)d_in[3];
    const float* bQ = (const float*)d_in[4];
    const float* WK = (const float*)d_in[5];
    const float* bK = (const float*)d_in[6];

    proj_q_kernel<<<dim3(128, 8), 256>>>(Q, WQ, bQ);
    proj_t_kernel<<<dim3(DD/ESL, 8), 256>>>(WK, bK);
    logits_kernel<<<256, 256>>>(K, (float4*)d_out);
    wsum_kernel<<<PGRID, 256>>>(V, (float4*)d_out);
}